// round 1
// baseline (speedup 1.0000x reference)
#include <cuda_runtime.h>
#include <math.h>
#include <stdint.h>

// FCOS post-process, GB300 (sm_103a)
// Stages: zero -> score+hist -> find byte threshold -> compact candidates ->
//         refine+bitonic sort (exact top-1000 w/ stable ties) -> decode boxes ->
//         IoU suppression mask -> sequential greedy NMS + output scatter.

#define NIMG 8
#define NCLS 80
#define HH   100
#define WW   152
#define PP   (HH*WW)          // 15200
#define CPE  (NCLS*PP)        // 1216000 elements per image
#define TOPK 1000
#define KPAD 1024
#define CAP  262144           // candidate compaction capacity per image
#define CAP2 2048             // final sort width (power of two >= 1000 + ties)
#define CHUNK 2048
#define NBLK ((CPE + CHUNK - 1)/CHUNK)   // 594 blocks per image

// ---------------- device scratch (static: no allocations allowed) ------------
__device__ unsigned long long g_cand[NIMG][CAP];     // 16 MB
__device__ unsigned long long g_top[NIMG][TOPK];
__device__ unsigned int g_hist[NIMG][256];
__device__ unsigned int g_candcnt[NIMG];
__device__ unsigned int g_b1[NIMG];
__device__ float g_box [NIMG][KPAD][4];
__device__ float g_obox[NIMG][KPAD][4];
__device__ float g_area[NIMG][KPAD];
__device__ float g_lab [NIMG][KPAD];
__device__ float g_sc  [NIMG][KPAD];
__device__ unsigned int g_validbits[NIMG][32];
__device__ unsigned int g_mask[NIMG][KPAD][32];      // 1 MB

__device__ __forceinline__ float sigmoidf_(float x) {
    return 1.0f / (1.0f + expf(-x));
}

// ---------------- 0: zero per-call state + output ---------------------------
__global__ void k_zero(float* out) {
    int t = blockIdx.x * blockDim.x + threadIdx.x;
    if (t < NIMG * 100 * 6) out[t] = 0.0f;
    if (t < NIMG * 256) ((unsigned int*)g_hist)[t] = 0u;
    if (t < NIMG) g_candcnt[t] = 0u;
}

// ---------------- 1: scores + top-byte histogram (pass 1 over cls) ----------
__global__ __launch_bounds__(256) void k_score_hist(const float* __restrict__ cls,
                                                    const float* __restrict__ ctr) {
    __shared__ unsigned int sh[256];
    int n = blockIdx.y;
    int t = threadIdx.x;
    if (t < 256) sh[t] = 0u;
    __syncthreads();
    int base = blockIdx.x * CHUNK;
    const float* clsn = cls + (size_t)n * CPE;
    const float* ctrn = ctr + (size_t)n * PP;
#pragma unroll
    for (int k = 0; k < 8; k++) {
        int j = base + t + k * 256;
        if (j < CPE) {
            int p = j % PP;
            float s = sigmoidf_(clsn[j]);
            if (s > 0.05f) {
                float score = __fmul_rn(s, sigmoidf_(ctrn[p]));
                unsigned b = __float_as_uint(score) >> 24;
                if (b) atomicAdd(&sh[b], 1u);
            }
        }
    }
    __syncthreads();
    if (t < 256 && sh[t]) atomicAdd(&g_hist[n][t], sh[t]);
}

// ---------------- 2: find top-byte threshold per image ----------------------
__global__ void k_findb1() {
    int n = threadIdx.x;
    if (n < NIMG) {
        unsigned cum = 0, b1 = 1;
        for (int b = 255; b >= 1; b--) {
            cum += g_hist[n][b];
            if (cum >= TOPK) { b1 = (unsigned)b; break; }
        }
        g_b1[n] = b1;
    }
}

// ---------------- 3: compact candidates >= byte threshold (pass 2) ----------
__global__ __launch_bounds__(256) void k_compact(const float* __restrict__ cls,
                                                 const float* __restrict__ ctr) {
    int n = blockIdx.y;
    int t = threadIdx.x;
    unsigned b1 = g_b1[n];
    int base = blockIdx.x * CHUNK;
    const float* clsn = cls + (size_t)n * CPE;
    const float* ctrn = ctr + (size_t)n * PP;
#pragma unroll
    for (int k = 0; k < 8; k++) {
        int j = base + t + k * 256;
        if (j < CPE) {
            int p = j % PP;
            float s = sigmoidf_(clsn[j]);
            if (s > 0.05f) {
                float score = __fmul_rn(s, sigmoidf_(ctrn[p]));
                unsigned sb = __float_as_uint(score);
                if ((sb >> 24) >= b1) {
                    int c = j / PP;
                    unsigned i = (unsigned)(p * NCLS + c);   // jax flat index p*C + c
                    unsigned long long key =
                        ((unsigned long long)sb << 32) |
                        (unsigned long long)(0xFFFFFFFFu - i); // smaller idx wins ties
                    unsigned pos = atomicAdd(&g_candcnt[n], 1u);
                    if (pos < CAP) g_cand[n][pos] = key;
                }
            }
        }
    }
}

// ---------------- 4: byte-level refine to exact s*, then bitonic top-1000 ---
__global__ __launch_bounds__(1024) void k_refine_sort() {
    __shared__ unsigned long long slist[CAP2];
    __shared__ unsigned int shist[256];
    __shared__ unsigned int s_pfx, s_r, s_cnt2;
    int n = blockIdx.x;
    int t = threadIdx.x;
    unsigned M = g_candcnt[n];
    if (M > CAP) M = CAP;
    if (t == 0) { s_pfx = 0u; s_r = TOPK; s_cnt2 = 0u; }
    __syncthreads();
    for (int lvl = 3; lvl >= 0; lvl--) {
        if (t < 256) shist[t] = 0u;
        __syncthreads();
        unsigned pfx = s_pfx;
        for (unsigned idx = t; idx < M; idx += 1024) {
            unsigned bits = (unsigned)(g_cand[n][idx] >> 32);
            bool cond = (lvl == 3) || ((bits >> ((lvl + 1) * 8)) == pfx);
            if (cond) atomicAdd(&shist[(bits >> (lvl * 8)) & 255u], 1u);
        }
        __syncthreads();
        if (t == 0) {
            unsigned cum = 0, rr = s_r; int chosen = 0;
            for (int b = 255; b >= 0; b--) {
                cum += shist[b];
                if (cum >= rr) { chosen = b; s_r = rr - (cum - shist[b]); break; }
            }
            s_pfx = (s_pfx << 8) | (unsigned)chosen;
        }
        __syncthreads();
    }
    unsigned sstar = s_pfx;  // exact 32-bit score-bits threshold (inclusive)
    for (int q = t; q < CAP2; q += 1024) slist[q] = 0ull;
    __syncthreads();
    for (unsigned idx = t; idx < M; idx += 1024) {
        unsigned long long key = g_cand[n][idx];
        if ((unsigned)(key >> 32) >= sstar) {
            unsigned pos = atomicAdd(&s_cnt2, 1u);
            if (pos < CAP2) slist[pos] = key;
        }
    }
    __syncthreads();
    // bitonic sort, descending, CAP2 elements, 1024 threads (1 compare each/step)
    for (int k2 = 2; k2 <= CAP2; k2 <<= 1) {
        for (int s = k2 >> 1; s >= 1; s >>= 1) {
            int i = ((t & ~(s - 1)) << 1) | (t & (s - 1));
            int l = i | s;
            unsigned long long a = slist[i], b = slist[l];
            bool dir = ((i & k2) == 0);
            if ((a < b) == dir) { slist[i] = b; slist[l] = a; }
            __syncthreads();
        }
    }
    if (t < TOPK) g_top[n][t] = slist[t];
}

// ---------------- 5: decode boxes, labels, offset boxes, validity -----------
__global__ __launch_bounds__(1024) void k_decode(const float* __restrict__ loc,
                                                 const float* __restrict__ reg,
                                                 const float* __restrict__ info) {
    int n = blockIdx.x;
    int t = threadIdx.x;
    float x1 = 0, y1 = 0, x2 = 0, y2 = 0, labf = 0, score = 0;
    float ox1 = 0, oy1 = 0, ox2 = 0, oy2 = 0, area = 0;
    bool valid = false;
    if (t < TOPK) {
        unsigned long long key = g_top[n][t];
        unsigned sb = (unsigned)(key >> 32);
        if (sb) {
            score = __uint_as_float(sb);
            unsigned i = 0xFFFFFFFFu - (unsigned)(key & 0xFFFFFFFFull);
            int p = (int)(i / NCLS);
            int c = (int)(i - (unsigned)(p * NCLS));
            labf = (float)(c + 1);
            float lx = loc[2 * p], ly = loc[2 * p + 1];
            float rl = reg[((size_t)(n * 4 + 0)) * PP + p];
            float rt = reg[((size_t)(n * 4 + 1)) * PP + p];
            float rr = reg[((size_t)(n * 4 + 2)) * PP + p];
            float rb = reg[((size_t)(n * 4 + 3)) * PP + p];
            float hm1 = __fsub_rn(info[2 * n + 0], 1.0f);
            float wm1 = __fsub_rn(info[2 * n + 1], 1.0f);
            x1 = fminf(fmaxf(__fsub_rn(lx, rl), 0.0f), wm1);
            y1 = fminf(fmaxf(__fsub_rn(ly, rt), 0.0f), hm1);
            x2 = fminf(fmaxf(__fadd_rn(lx, rr), 0.0f), wm1);
            y2 = fminf(fmaxf(__fadd_rn(ly, rb), 0.0f), hm1);
            valid = (score > 0.0f) &&
                    (__fsub_rn(x2, x1) >= 0.0f) && (__fsub_rn(y2, y1) >= 0.0f);
            float off = __fmul_rn(labf, 1.0e5f);   // class-offset trick, fp32 like ref
            ox1 = __fadd_rn(x1, off); oy1 = __fadd_rn(y1, off);
            ox2 = __fadd_rn(x2, off); oy2 = __fadd_rn(y2, off);
            area = __fmul_rn(fmaxf(__fsub_rn(ox2, ox1), 0.0f),
                             fmaxf(__fsub_rn(oy2, oy1), 0.0f));
        }
    }
    g_box[n][t][0] = x1; g_box[n][t][1] = y1; g_box[n][t][2] = x2; g_box[n][t][3] = y2;
    g_obox[n][t][0] = ox1; g_obox[n][t][1] = oy1; g_obox[n][t][2] = ox2; g_obox[n][t][3] = oy2;
    g_area[n][t] = area; g_lab[n][t] = labf; g_sc[n][t] = score;
    unsigned bal = __ballot_sync(0xffffffffu, valid);
    if ((t & 31) == 0) g_validbits[n][t >> 5] = bal;
}

// ---------------- 6: suppression bitmask (j > i, IoU > 0.6) -----------------
__global__ __launch_bounds__(128) void k_mask() {
    __shared__ float4 sob[KPAD];
    __shared__ float  sar[KPAD];
    __shared__ float  slb[KPAD];
    int n = blockIdx.y;
    int t = threadIdx.x;
    for (int q = t; q < KPAD; q += 128) {
        sob[q] = *(const float4*)&g_obox[n][q][0];
        sar[q] = g_area[n][q];
        slb[q] = g_lab[n][q];
    }
    __syncthreads();
    int i = blockIdx.x * 128 + t;
    float4 bi = sob[i];
    float ai = sar[i];
    float li = slb[i];
    int wlo = i >> 5;
    for (int w = 0; w < 32; w++) {
        unsigned bits = 0u;
        if (w >= wlo) {
            int jb = w * 32;
#pragma unroll
            for (int b = 0; b < 32; b++) {
                int j = jb + b;
                if (j > i && slb[j] == li) {   // cross-class offset => IoU exactly 0
                    float4 bj = sob[j];
                    float wv = fmaxf(__fsub_rn(fminf(bi.z, bj.z), fmaxf(bi.x, bj.x)), 0.0f);
                    float hv = fmaxf(__fsub_rn(fminf(bi.w, bj.w), fmaxf(bi.y, bj.y)), 0.0f);
                    float inter = __fmul_rn(wv, hv);
                    float denom = __fadd_rn(__fsub_rn(__fadd_rn(ai, sar[j]), inter), 1e-9f);
                    if (__fdiv_rn(inter, denom) > 0.6f) bits |= (1u << b);
                }
            }
        }
        g_mask[n][i][w] = bits;
    }
}

// ---------------- 7: sequential greedy NMS (1 warp/image) + output ----------
__global__ __launch_bounds__(32) void k_nms_out(float* __restrict__ out) {
    __shared__ unsigned int sm[1024];   // 32 rows x 32 words prefetch tile
    int n = blockIdx.x;
    int lane = threadIdx.x;
    unsigned validw = g_validbits[n][lane];
    unsigned removew = 0u;
    for (int g = 0; g < 32; g++) {
        for (int r = 0; r < 32; r++)
            sm[r * 32 + lane] = g_mask[n][g * 32 + r][lane];
        __syncwarp();
        unsigned cur_sup = __shfl_sync(0xffffffffu, removew, g);
        unsigned cur_val = __shfl_sync(0xffffffffu, validw, g);
        unsigned rowv[32], diag[32];
#pragma unroll
        for (int b = 0; b < 32; b++) { rowv[b] = sm[b * 32 + lane]; diag[b] = sm[b * 32 + g]; }
#pragma unroll
        for (int b = 0; b < 32; b++) {
            bool alive = ((cur_val >> b) & 1u) && !((cur_sup >> b) & 1u);
            if (alive) { removew |= rowv[b]; cur_sup |= diag[b]; }
        }
        __syncwarp();
    }
    unsigned keepw = validw & ~removew;
    int cnt = __popc(keepw);
    int inc = cnt;
    for (int o = 1; o < 32; o <<= 1) {
        int v = __shfl_up_sync(0xffffffffu, inc, o);
        if (lane >= o) inc += v;
    }
    int basei = inc - cnt;           // exclusive prefix of kept count
    unsigned m = keepw;
    while (m) {
        int b = __ffs(m) - 1;
        m &= m - 1;
        int rank = basei + __popc(keepw & ((1u << b) - 1u));
        if (rank < 100) {
            int i = lane * 32 + b;
            float* o6 = out + ((size_t)n * 100 + rank) * 6;
            o6[0] = g_box[n][i][0]; o6[1] = g_box[n][i][1];
            o6[2] = g_box[n][i][2]; o6[3] = g_box[n][i][3];
            o6[4] = g_lab[n][i];    o6[5] = g_sc[n][i];
        }
    }
}

// ---------------- launch -----------------------------------------------------
extern "C" void kernel_launch(void* const* d_in, const int* in_sizes, int n_in,
                              void* d_out, int out_size) {
    const float* loc  = (const float*)d_in[0];   // [P,2]
    const float* cls  = (const float*)d_in[1];   // [N,C,H,W]
    const float* reg  = (const float*)d_in[2];   // [N,4,H,W]
    const float* ctr  = (const float*)d_in[3];   // [N,1,H,W]
    const float* info = (const float*)d_in[4];   // [N,2]
    float* out = (float*)d_out;                  // [N,100,6]
    (void)in_sizes; (void)n_in; (void)out_size;

    k_zero<<<5, 1024>>>(out);
    dim3 g2(NBLK, NIMG);
    k_score_hist<<<g2, 256>>>(cls, ctr);
    k_findb1<<<1, 32>>>();
    k_compact<<<g2, 256>>>(cls, ctr);
    k_refine_sort<<<NIMG, 1024>>>();
    k_decode<<<NIMG, 1024>>>(loc, reg, info);
    dim3 gm(8, NIMG);
    k_mask<<<gm, 128>>>();
    k_nms_out<<<NIMG, 32>>>(out);
}